// round 6
// baseline (speedup 1.0000x reference)
#include <cuda_runtime.h>
#include <cstdint>
#include <cstddef>

#define NN 100000
#define NE 640000
#define IN_CH 128
#define HID 256
#define OC 64

// ---------------- scratch (static device globals; 16B-aligned) ----------------
// Kernels reference these DIRECTLY by symbol: compile-time .global addressing.
__device__ __align__(16) float g_cnt[NN];                   // degree -> inverse degree
__device__ __align__(16) float g_agg1[(size_t)NN * IN_CH];  // sum of x over in-edges
__device__ __align__(16) float g_h[(size_t)NN * HID];       // layer-1 output (post ReLU)
__device__ __align__(16) float g_P[(size_t)NN * OC];        // h @ W2l^T (pre-aggregation)
__device__ __align__(16) float g_agg2[(size_t)NN * OC];     // sum of P over in-edges

// ---------------- zero scratch ----------------
#define CNT_F4   (NN / 4)
#define AGG1_F4  ((size_t)NN * IN_CH / 4)
#define AGG2_F4  ((size_t)NN * OC / 4)
#define ZERO_F4  (CNT_F4 + AGG1_F4 + AGG2_F4)

__global__ void zero_kernel() {
    size_t i = (size_t)blockIdx.x * blockDim.x + threadIdx.x;
    if (i >= ZERO_F4) return;
    float4 z = make_float4(0.f, 0.f, 0.f, 0.f);
    if (i < CNT_F4) {
        ((float4*)g_cnt)[i] = z;
    } else if (i < CNT_F4 + AGG1_F4) {
        ((float4*)g_agg1)[i - CNT_F4] = z;
    } else {
        ((float4*)g_agg2)[i - CNT_F4 - AGG1_F4] = z;
    }
}

// index sanitizer: valid data is 0..NN-1; clamp so garbage can never trap.
__device__ __forceinline__ int clampN(int v) {
    return ((unsigned)v < (unsigned)NN) ? v : 0;
}

// ---------------- degree count + inverse ----------------
// edge_index is INT32 (JAX default x64-disabled downcasts the reference's int64).
__global__ void count_kernel(const int* __restrict__ ei) {
    int e = blockIdx.x * blockDim.x + threadIdx.x;
    if (e < NE) {
        int dst = clampN(ei[NE + e]);
        atomicAdd(&g_cnt[dst], 1.0f);
    }
}
__global__ void inv_kernel() {
    int i = blockIdx.x * blockDim.x + threadIdx.x;
    if (i < NN) g_cnt[i] = 1.0f / fmaxf(g_cnt[i], 1.0f);
}

// ---------------- scatter1: g_agg1[dst] += x[src] (128 ch) ----------------
__global__ void scatter1_kernel(const int* __restrict__ ei,
                                const float* __restrict__ x) {
    constexpr int Q = IN_CH / 4;                      // 32 float4 per row
    int gt = blockIdx.x * blockDim.x + threadIdx.x;
    int e = gt >> 5;
    int q = gt & 31;
    if (e >= NE) return;
    int s = clampN(ei[e]);
    int d = clampN(ei[NE + e]);
    float4 v = *((const float4*)x + (size_t)s * Q + q);
    float* base = g_agg1 + (size_t)d * IN_CH + q * 4;
    atomicAdd(base + 0, v.x);
    atomicAdd(base + 1, v.y);
    atomicAdd(base + 2, v.z);
    atomicAdd(base + 3, v.w);
}

// ---------------- scatter2: g_agg2[dst] += g_P[src] (64 ch) ----------------
__global__ void scatter2_kernel(const int* __restrict__ ei) {
    constexpr int Q = OC / 4;                         // 16 float4 per row
    int gt = blockIdx.x * blockDim.x + threadIdx.x;
    int e = gt >> 4;
    int q = gt & 15;
    if (e >= NE) return;
    int s = clampN(ei[e]);
    int d = clampN(ei[NE + e]);
    float4 v = *((const float4*)g_P + (size_t)s * Q + q);
    float* base = g_agg2 + (size_t)d * OC + q * 4;
    atomicAdd(base + 0, v.x);
    atomicAdd(base + 1, v.y);
    atomicAdd(base + 2, v.z);
    atomicAdd(base + 3, v.w);
}

// ---------------- layer-1 fused GEMM ----------------
// h[n,c] = relu( mean[n,:] . W1l[c,:] + x[n,:] . W1r[c,:] + b1[c] )
// concat-K GEMM: K = 256, first 128 from (agg1 * inv), last 128 from x.
// BM=64, BN=128, BK=32, TM=4, TN=8, 256 threads, plain FFMA.
__global__ void __launch_bounds__(256)
gemm1_kernel(const float* __restrict__ x,
             const float* __restrict__ W1l,
             const float* __restrict__ W1r,
             const float* __restrict__ b1) {
    constexpr int BM = 64, BN = 128, BK = 32, TM = 4, TN = 8, K0 = 128;
    __shared__ float As[BK][BM + 4];
    __shared__ float Bs[BK][BN + 4];

    const int tid = threadIdx.x;
    const int tx = tid & 15;   // BN/TN = 16
    const int ty = tid >> 4;   // BM/TM = 16
    const int rowBase = blockIdx.x * BM;
    const int colBase = blockIdx.y * BN;

    float acc[TM][TN];
#pragma unroll
    for (int i = 0; i < TM; i++)
#pragma unroll
        for (int j = 0; j < TN; j++) acc[i][j] = 0.0f;

#pragma unroll 1
    for (int kt = 0; kt < 8; kt++) {
        const bool first = kt < 4;
        const int koff = first ? kt * BK : kt * BK - K0;
        const float* Asrc = first ? g_agg1 : x;
        const float* Bsrc = first ? W1l : W1r;

        // A tile: 64x32 = 512 float4, 2 per thread
#pragma unroll
        for (int i = 0; i < 2; i++) {
            int idx = tid + i * 256;
            int r = idx >> 3;
            int kq = idx & 7;
            int n = rowBase + r; if (n >= NN) n = NN - 1;
            float4 v = *(const float4*)(Asrc + (size_t)n * K0 + koff + kq * 4);
            if (first) {
                float s = g_cnt[n];
                v.x *= s; v.y *= s; v.z *= s; v.w *= s;
            }
            As[kq * 4 + 0][r] = v.x; As[kq * 4 + 1][r] = v.y;
            As[kq * 4 + 2][r] = v.z; As[kq * 4 + 3][r] = v.w;
        }
        // B tile: 128x32 = 1024 float4, 4 per thread
#pragma unroll
        for (int i = 0; i < 4; i++) {
            int idx = tid + i * 256;
            int j = idx >> 3;
            int kq = idx & 7;
            float4 v = *(const float4*)(Bsrc + (size_t)(colBase + j) * K0 + koff + kq * 4);
            Bs[kq * 4 + 0][j] = v.x; Bs[kq * 4 + 1][j] = v.y;
            Bs[kq * 4 + 2][j] = v.z; Bs[kq * 4 + 3][j] = v.w;
        }
        __syncthreads();

#pragma unroll
        for (int kk = 0; kk < BK; kk++) {
            float4 a0 = *(const float4*)&As[kk][ty * TM];
            float4 bb0 = *(const float4*)&Bs[kk][tx * TN];
            float4 bb1 = *(const float4*)&Bs[kk][tx * TN + 4];
            float a[TM] = {a0.x, a0.y, a0.z, a0.w};
            float b[TN] = {bb0.x, bb0.y, bb0.z, bb0.w, bb1.x, bb1.y, bb1.z, bb1.w};
#pragma unroll
            for (int i = 0; i < TM; i++)
#pragma unroll
                for (int j = 0; j < TN; j++)
                    acc[i][j] = fmaf(a[i], b[j], acc[i][j]);
        }
        __syncthreads();
    }

#pragma unroll
    for (int i = 0; i < TM; i++) {
        int n = rowBase + ty * TM + i;
        if (n < NN) {
#pragma unroll
            for (int j = 0; j < TN; j += 4) {
                int c = colBase + tx * TN + j;
                float4 st;
                st.x = fmaxf(acc[i][j + 0] + b1[c + 0], 0.0f);
                st.y = fmaxf(acc[i][j + 1] + b1[c + 1], 0.0f);
                st.z = fmaxf(acc[i][j + 2] + b1[c + 2], 0.0f);
                st.w = fmaxf(acc[i][j + 3] + b1[c + 3], 0.0f);
                *(float4*)&g_h[(size_t)n * HID + c] = st;
            }
        }
    }
}

// ---------------- layer-2 GEMMs: C = h @ W^T (K=256, J=64) ----------------
// blockIdx.y == 0: W = W2l, C = g_P   (pre-aggregation linear)
// blockIdx.y == 1: W = W2r, C = out   (self linear, raw; bias in finalize)
// BM=128, BN=64, BK=32, TM=4, TN=8, 256 threads.
__global__ void __launch_bounds__(256)
gemm2_kernel(const float* __restrict__ W2l,
             const float* __restrict__ W2r,
             float* __restrict__ outRaw) {
    constexpr int BM = 128, BN = 64, BK = 32, TM = 4, TN = 8, K = 256;
    __shared__ float As[BK][BM + 4];
    __shared__ float Bs[BK][BN + 4];

    const float* W = (blockIdx.y == 0) ? W2l : W2r;
    float* C = (blockIdx.y == 0) ? g_P : outRaw;

    const int tid = threadIdx.x;
    const int tx = tid & 7;    // BN/TN = 8
    const int ty = tid >> 3;   // BM/TM = 32
    const int rowBase = blockIdx.x * BM;

    float acc[TM][TN];
#pragma unroll
    for (int i = 0; i < TM; i++)
#pragma unroll
        for (int j = 0; j < TN; j++) acc[i][j] = 0.0f;

#pragma unroll 1
    for (int kt = 0; kt < 8; kt++) {
        const int koff = kt * BK;
        // A tile: 128x32 = 1024 float4, 4 per thread
#pragma unroll
        for (int i = 0; i < 4; i++) {
            int idx = tid + i * 256;
            int r = idx >> 3;
            int kq = idx & 7;
            int n = rowBase + r; if (n >= NN) n = NN - 1;
            float4 v = *(const float4*)(g_h + (size_t)n * K + koff + kq * 4);
            As[kq * 4 + 0][r] = v.x; As[kq * 4 + 1][r] = v.y;
            As[kq * 4 + 2][r] = v.z; As[kq * 4 + 3][r] = v.w;
        }
        // B tile: 64x32 = 512 float4, 2 per thread
#pragma unroll
        for (int i = 0; i < 2; i++) {
            int idx = tid + i * 256;
            int j = idx >> 3;
            int kq = idx & 7;
            float4 v = *(const float4*)(W + (size_t)j * K + koff + kq * 4);
            Bs[kq * 4 + 0][j] = v.x; Bs[kq * 4 + 1][j] = v.y;
            Bs[kq * 4 + 2][j] = v.z; Bs[kq * 4 + 3][j] = v.w;
        }
        __syncthreads();

#pragma unroll
        for (int kk = 0; kk < BK; kk++) {
            float4 a0 = *(const float4*)&As[kk][ty * TM];
            float4 bb0 = *(const float4*)&Bs[kk][tx * TN];
            float4 bb1 = *(const float4*)&Bs[kk][tx * TN + 4];
            float a[TM] = {a0.x, a0.y, a0.z, a0.w};
            float b[TN] = {bb0.x, bb0.y, bb0.z, bb0.w, bb1.x, bb1.y, bb1.z, bb1.w};
#pragma unroll
            for (int i = 0; i < TM; i++)
#pragma unroll
                for (int j = 0; j < TN; j++)
                    acc[i][j] = fmaf(a[i], b[j], acc[i][j]);
        }
        __syncthreads();
    }

#pragma unroll
    for (int i = 0; i < TM; i++) {
        int n = rowBase + ty * TM + i;
        if (n < NN) {
#pragma unroll
            for (int j = 0; j < TN; j += 4) {
                int c = tx * TN + j;
                float4 st;
                st.x = acc[i][j + 0]; st.y = acc[i][j + 1];
                st.z = acc[i][j + 2]; st.w = acc[i][j + 3];
                *(float4*)&C[(size_t)n * OC + c] = st;
            }
        }
    }
}

// ---------------- finalize: out += inv * agg2 + b2 ----------------
__global__ void finalize_kernel(const float* __restrict__ b2,
                                float* __restrict__ out) {
    int i = blockIdx.x * blockDim.x + threadIdx.x;   // float4 index
    if (i >= NN * (OC / 4)) return;
    int n = i / (OC / 4);
    int c4 = i % (OC / 4);
    float inv = g_cnt[n];
    float4 o = ((float4*)out)[i];
    float4 a = ((const float4*)g_agg2)[i];
    float4 b = ((const float4*)b2)[c4];
    o.x += inv * a.x + b.x;
    o.y += inv * a.y + b.y;
    o.z += inv * a.z + b.z;
    o.w += inv * a.w + b.w;
    ((float4*)out)[i] = o;
}

// ---------------- launch ----------------
extern "C" void kernel_launch(void* const* d_in, const int* in_sizes, int n_in,
                              void* d_out, int out_size) {
    const float* x   = (const float*)d_in[0];
    const int*   ei  = (const int*)d_in[1];      // int32! (JAX x64 disabled)
    const float* W1l = (const float*)d_in[2];
    const float* b1  = (const float*)d_in[3];
    const float* W1r = (const float*)d_in[4];
    const float* W2l = (const float*)d_in[5];
    const float* b2  = (const float*)d_in[6];
    const float* W2r = (const float*)d_in[7];
    float* out = (float*)d_out;

    // zero cnt/agg1/agg2
    zero_kernel<<<(unsigned)((ZERO_F4 + 255) / 256), 256>>>();

    count_kernel<<<(NE + 255) / 256, 256>>>(ei);
    inv_kernel<<<(NN + 255) / 256, 256>>>();

    // layer-1 aggregation: agg1[dst] += x[src]
    scatter1_kernel<<<(NE * 32 + 255) / 256, 256>>>(ei, x);

    // h = relu([agg1*inv | x] @ [W1l | W1r]^T + b1)
    gemm1_kernel<<<dim3((NN + 63) / 64, 2), 256>>>(x, W1l, W1r, b1);

    // P = h @ W2l^T ; out_raw = h @ W2r^T
    gemm2_kernel<<<dim3((NN + 127) / 128, 2), 256>>>(W2l, W2r, out);

    // layer-2 aggregation in output space: agg2[dst] += P[src]
    scatter2_kernel<<<(NE * 16 + 255) / 256, 256>>>(ei);

    // out = out_raw + inv * agg2 + b2
    finalize_kernel<<<(NN * (OC / 4) + 255) / 256, 256>>>(b2, out);
}

// round 7
// speedup vs baseline: 1.1007x; 1.1007x over previous
#include <cuda_runtime.h>
#include <cstdint>
#include <cstddef>

#define NN 100000
#define NE 640000
#define IN_CH 128
#define HID 256
#define OC 64

// ---------------- scratch (static device globals; 16B-aligned) ----------------
__device__ __align__(16) float g_cnt[NN];                   // degree -> inverse degree
__device__ __align__(16) float g_agg1[(size_t)NN * IN_CH];  // sum of x over in-edges
__device__ __align__(16) float g_h[(size_t)NN * HID];       // layer-1 output (post ReLU)
__device__ __align__(16) float g_P[(size_t)NN * OC];        // h @ W2l^T (pre-aggregation)
__device__ __align__(16) float g_agg2[(size_t)NN * OC];     // sum of P over in-edges

// ---------------- zero scratch ----------------
#define CNT_F4   (NN / 4)
#define AGG1_F4  ((size_t)NN * IN_CH / 4)
#define AGG2_F4  ((size_t)NN * OC / 4)
#define ZERO_F4  (CNT_F4 + AGG1_F4 + AGG2_F4)

__global__ void zero_kernel() {
    size_t i = (size_t)blockIdx.x * blockDim.x + threadIdx.x;
    if (i >= ZERO_F4) return;
    float4 z = make_float4(0.f, 0.f, 0.f, 0.f);
    if (i < CNT_F4) {
        ((float4*)g_cnt)[i] = z;
    } else if (i < CNT_F4 + AGG1_F4) {
        ((float4*)g_agg1)[i - CNT_F4] = z;
    } else {
        ((float4*)g_agg2)[i - CNT_F4 - AGG1_F4] = z;
    }
}

__device__ __forceinline__ int clampN(int v) {
    return ((unsigned)v < (unsigned)NN) ? v : 0;
}

// ---------------- packed f32x2 helpers ----------------
__device__ __forceinline__ unsigned long long ffma2(unsigned long long a,
                                                    unsigned long long b,
                                                    unsigned long long c) {
    unsigned long long d;
    asm("fma.rn.f32x2 %0, %1, %2, %3;" : "=l"(d) : "l"(a), "l"(b), "l"(c));
    return d;
}
__device__ __forceinline__ unsigned long long pack2(float v) {
    unsigned long long d;
    asm("mov.b64 %0, {%1, %1};" : "=l"(d) : "f"(v));
    return d;
}

// ---------------- degree count + inverse ----------------
__global__ void count_kernel(const int* __restrict__ ei) {
    int e = blockIdx.x * blockDim.x + threadIdx.x;
    if (e < NE) {
        int dst = clampN(ei[NE + e]);
        atomicAdd(&g_cnt[dst], 1.0f);
    }
}
__global__ void inv_kernel() {
    int i = blockIdx.x * blockDim.x + threadIdx.x;
    if (i < NN) g_cnt[i] = 1.0f / fmaxf(g_cnt[i], 1.0f);
}

// ---------------- scatter1: g_agg1[dst] += x[src] (128 ch), vector RED ----------------
__global__ void scatter1_kernel(const int* __restrict__ ei,
                                const float* __restrict__ x) {
    constexpr int Q = IN_CH / 4;                      // 32 float4 per row
    int gt = blockIdx.x * blockDim.x + threadIdx.x;
    int e = gt >> 5;
    int q = gt & 31;
    if (e >= NE) return;
    int s = clampN(ei[e]);
    int d = clampN(ei[NE + e]);
    float4 v = *((const float4*)x + (size_t)s * Q + q);
    atomicAdd((float4*)g_agg1 + (size_t)d * Q + q, v);
}

// ---------------- scatter2: g_agg2[dst] += g_P[src] (64 ch), vector RED ----------------
__global__ void scatter2_kernel(const int* __restrict__ ei) {
    constexpr int Q = OC / 4;                         // 16 float4 per row
    int gt = blockIdx.x * blockDim.x + threadIdx.x;
    int e = gt >> 4;
    int q = gt & 15;
    if (e >= NE) return;
    int s = clampN(ei[e]);
    int d = clampN(ei[NE + e]);
    float4 v = *((const float4*)g_P + (size_t)s * Q + q);
    atomicAdd((float4*)g_agg2 + (size_t)d * Q + q, v);
}

// ---------------- layer-1 fused GEMM (f32x2 packed accumulators) ----------------
// h[n,c] = relu( mean[n,:] . W1l[c,:] + x[n,:] . W1r[c,:] + b1[c] )
// concat-K GEMM: K = 256, first 128 from (agg1 * inv), last 128 from x.
// BM=64, BN=128, BK=32, TM=4, TN=8, 256 threads.
__global__ void __launch_bounds__(256)
gemm1_kernel(const float* __restrict__ x,
             const float* __restrict__ W1l,
             const float* __restrict__ W1r,
             const float* __restrict__ b1) {
    constexpr int BM = 64, BN = 128, BK = 32, TM = 4, TN = 8, K0 = 128;
    __shared__ float As[BK][BM + 4];
    __shared__ float Bs[BK][BN + 4];

    const int tid = threadIdx.x;
    const int tx = tid & 15;   // BN/TN = 16
    const int ty = tid >> 4;   // BM/TM = 16
    const int rowBase = blockIdx.x * BM;
    const int colBase = blockIdx.y * BN;

    unsigned long long acc[TM][TN / 2];
#pragma unroll
    for (int i = 0; i < TM; i++)
#pragma unroll
        for (int j = 0; j < TN / 2; j++) acc[i][j] = 0ull;

#pragma unroll 1
    for (int kt = 0; kt < 8; kt++) {
        const bool first = kt < 4;
        const int koff = first ? kt * BK : kt * BK - K0;
        const float* Asrc = first ? g_agg1 : x;
        const float* Bsrc = first ? W1l : W1r;

        // A tile: 64x32 = 512 float4, 2 per thread
#pragma unroll
        for (int i = 0; i < 2; i++) {
            int idx = tid + i * 256;
            int r = idx >> 3;
            int kq = idx & 7;
            int n = rowBase + r; if (n >= NN) n = NN - 1;
            float4 v = *(const float4*)(Asrc + (size_t)n * K0 + koff + kq * 4);
            if (first) {
                float s = g_cnt[n];
                v.x *= s; v.y *= s; v.z *= s; v.w *= s;
            }
            As[kq * 4 + 0][r] = v.x; As[kq * 4 + 1][r] = v.y;
            As[kq * 4 + 2][r] = v.z; As[kq * 4 + 3][r] = v.w;
        }
        // B tile: 128x32 = 1024 float4, 4 per thread
#pragma unroll
        for (int i = 0; i < 4; i++) {
            int idx = tid + i * 256;
            int j = idx >> 3;
            int kq = idx & 7;
            float4 v = *(const float4*)(Bsrc + (size_t)(colBase + j) * K0 + koff + kq * 4);
            Bs[kq * 4 + 0][j] = v.x; Bs[kq * 4 + 1][j] = v.y;
            Bs[kq * 4 + 2][j] = v.z; Bs[kq * 4 + 3][j] = v.w;
        }
        __syncthreads();

#pragma unroll
        for (int kk = 0; kk < BK; kk++) {
            float4 av = *(const float4*)&As[kk][ty * TM];
            unsigned long long ap[TM];
            ap[0] = pack2(av.x); ap[1] = pack2(av.y);
            ap[2] = pack2(av.z); ap[3] = pack2(av.w);
            ulonglong2 b0 = *(const ulonglong2*)&Bs[kk][tx * TN];
            ulonglong2 b1v = *(const ulonglong2*)&Bs[kk][tx * TN + 4];
            unsigned long long bp[TN / 2] = {b0.x, b0.y, b1v.x, b1v.y};
#pragma unroll
            for (int i = 0; i < TM; i++)
#pragma unroll
                for (int j = 0; j < TN / 2; j++)
                    acc[i][j] = ffma2(ap[i], bp[j], acc[i][j]);
        }
        __syncthreads();
    }

#pragma unroll
    for (int i = 0; i < TM; i++) {
        int n = rowBase + ty * TM + i;
        if (n < NN) {
#pragma unroll
            for (int j = 0; j < TN / 2; j++) {
                int c = colBase + tx * TN + 2 * j;
                float lo = __uint_as_float((unsigned)(acc[i][j] & 0xffffffffull));
                float hi = __uint_as_float((unsigned)(acc[i][j] >> 32));
                lo = fmaxf(lo + b1[c], 0.0f);
                hi = fmaxf(hi + b1[c + 1], 0.0f);
                float2 st; st.x = lo; st.y = hi;
                *(float2*)&g_h[(size_t)n * HID + c] = st;
            }
        }
    }
}

// ---------------- layer-2 GEMMs: C = h @ W^T (K=256, J=64), f32x2 ----------------
// blockIdx.y == 0: W = W2l, C = g_P   (pre-aggregation linear)
// blockIdx.y == 1: W = W2r, C = out   (self linear, raw; bias in finalize)
// BM=128, BN=64, BK=32, TM=4, TN=8, 256 threads.
__global__ void __launch_bounds__(256)
gemm2_kernel(const float* __restrict__ W2l,
             const float* __restrict__ W2r,
             float* __restrict__ outRaw) {
    constexpr int BM = 128, BN = 64, BK = 32, TM = 4, TN = 8, K = 256;
    __shared__ float As[BK][BM + 4];
    __shared__ float Bs[BK][BN + 4];

    const float* W = (blockIdx.y == 0) ? W2l : W2r;
    float* C = (blockIdx.y == 0) ? g_P : outRaw;

    const int tid = threadIdx.x;
    const int tx = tid & 7;    // BN/TN = 8
    const int ty = tid >> 3;   // BM/TM = 32
    const int rowBase = blockIdx.x * BM;

    unsigned long long acc[TM][TN / 2];
#pragma unroll
    for (int i = 0; i < TM; i++)
#pragma unroll
        for (int j = 0; j < TN / 2; j++) acc[i][j] = 0ull;

#pragma unroll 1
    for (int kt = 0; kt < 8; kt++) {
        const int koff = kt * BK;
        // A tile: 128x32 = 1024 float4, 4 per thread
#pragma unroll
        for (int i = 0; i < 4; i++) {
            int idx = tid + i * 256;
            int r = idx >> 3;
            int kq = idx & 7;
            int n = rowBase + r; if (n >= NN) n = NN - 1;
            float4 v = *(const float4*)(g_h + (size_t)n * K + koff + kq * 4);
            As[kq * 4 + 0][r] = v.x; As[kq * 4 + 1][r] = v.y;
            As[kq * 4 + 2][r] = v.z; As[kq * 4 + 3][r] = v.w;
        }
        // B tile: 64x32 = 512 float4, 2 per thread
#pragma unroll
        for (int i = 0; i < 2; i++) {
            int idx = tid + i * 256;
            int j = idx >> 3;
            int kq = idx & 7;
            float4 v = *(const float4*)(W + (size_t)j * K + koff + kq * 4);
            Bs[kq * 4 + 0][j] = v.x; Bs[kq * 4 + 1][j] = v.y;
            Bs[kq * 4 + 2][j] = v.z; Bs[kq * 4 + 3][j] = v.w;
        }
        __syncthreads();

#pragma unroll
        for (int kk = 0; kk < BK; kk++) {
            float4 av = *(const float4*)&As[kk][ty * TM];
            unsigned long long ap[TM];
            ap[0] = pack2(av.x); ap[1] = pack2(av.y);
            ap[2] = pack2(av.z); ap[3] = pack2(av.w);
            ulonglong2 b0 = *(const ulonglong2*)&Bs[kk][tx * TN];
            ulonglong2 b1v = *(const ulonglong2*)&Bs[kk][tx * TN + 4];
            unsigned long long bp[TN / 2] = {b0.x, b0.y, b1v.x, b1v.y};
#pragma unroll
            for (int i = 0; i < TM; i++)
#pragma unroll
                for (int j = 0; j < TN / 2; j++)
                    acc[i][j] = ffma2(ap[i], bp[j], acc[i][j]);
        }
        __syncthreads();
    }

#pragma unroll
    for (int i = 0; i < TM; i++) {
        int n = rowBase + ty * TM + i;
        if (n < NN) {
#pragma unroll
            for (int j = 0; j < TN / 2; j++) {
                int c = tx * TN + 2 * j;
                float2 st;
                st.x = __uint_as_float((unsigned)(acc[i][j] & 0xffffffffull));
                st.y = __uint_as_float((unsigned)(acc[i][j] >> 32));
                *(float2*)&C[(size_t)n * OC + c] = st;
            }
        }
    }
}

// ---------------- finalize: out += inv * agg2 + b2 ----------------
__global__ void finalize_kernel(const float* __restrict__ b2,
                                float* __restrict__ out) {
    int i = blockIdx.x * blockDim.x + threadIdx.x;   // float4 index
    if (i >= NN * (OC / 4)) return;
    int n = i / (OC / 4);
    int c4 = i % (OC / 4);
    float inv = g_cnt[n];
    float4 o = ((float4*)out)[i];
    float4 a = ((const float4*)g_agg2)[i];
    float4 b = ((const float4*)b2)[c4];
    o.x += inv * a.x + b.x;
    o.y += inv * a.y + b.y;
    o.z += inv * a.z + b.z;
    o.w += inv * a.w + b.w;
    ((float4*)out)[i] = o;
}

// ---------------- launch ----------------
extern "C" void kernel_launch(void* const* d_in, const int* in_sizes, int n_in,
                              void* d_out, int out_size) {
    const float* x   = (const float*)d_in[0];
    const int*   ei  = (const int*)d_in[1];      // int32 (JAX x64 disabled)
    const float* W1l = (const float*)d_in[2];
    const float* b1  = (const float*)d_in[3];
    const float* W1r = (const float*)d_in[4];
    const float* W2l = (const float*)d_in[5];
    const float* b2  = (const float*)d_in[6];
    const float* W2r = (const float*)d_in[7];
    float* out = (float*)d_out;

    zero_kernel<<<(unsigned)((ZERO_F4 + 255) / 256), 256>>>();

    count_kernel<<<(NE + 255) / 256, 256>>>(ei);
    inv_kernel<<<(NN + 255) / 256, 256>>>();

    // layer-1 aggregation: agg1[dst] += x[src]
    scatter1_kernel<<<(NE * 32 + 255) / 256, 256>>>(ei, x);

    // h = relu([agg1*inv | x] @ [W1l | W1r]^T + b1)
    gemm1_kernel<<<dim3((NN + 63) / 64, 2), 256>>>(x, W1l, W1r, b1);

    // P = h @ W2l^T ; out_raw = h @ W2r^T
    gemm2_kernel<<<dim3((NN + 127) / 128, 2), 256>>>(W2l, W2r, out);

    // layer-2 aggregation in output space: agg2[dst] += P[src]
    scatter2_kernel<<<(NE * 16 + 255) / 256, 256>>>(ei);

    // out = out_raw + inv * agg2 + b2
    finalize_kernel<<<(NN * (OC / 4) + 255) / 256, 256>>>(b2, out);
}

// round 8
// speedup vs baseline: 2.6390x; 2.3975x over previous
#include <cuda_runtime.h>
#include <cstdint>
#include <cstddef>

#define NN 100000
#define NE 640000
#define IN_CH 128
#define HID 256
#define OC 64

// ---------------- scratch ----------------
__device__ __align__(16) float g_cnt[NN];
__device__ __align__(16) float g_agg1[(size_t)NN * IN_CH];
__device__ __align__(16) float g_h[(size_t)NN * HID];
__device__ __align__(16) float g_P[(size_t)NN * OC];
__device__ __align__(16) float g_agg2[(size_t)NN * OC];

#define CNT_F4   (NN / 4)
#define AGG1_F4  ((size_t)NN * IN_CH / 4)
#define AGG2_F4  ((size_t)NN * OC / 4)
#define ZERO_F4  (CNT_F4 + AGG1_F4 + AGG2_F4)

__global__ void zero_kernel() {
    size_t i = (size_t)blockIdx.x * blockDim.x + threadIdx.x;
    if (i >= ZERO_F4) return;
    float4 z = make_float4(0.f, 0.f, 0.f, 0.f);
    if (i < CNT_F4)                  ((float4*)g_cnt)[i] = z;
    else if (i < CNT_F4 + AGG1_F4)   ((float4*)g_agg1)[i - CNT_F4] = z;
    else                             ((float4*)g_agg2)[i - CNT_F4 - AGG1_F4] = z;
}

__device__ __forceinline__ int clampN(int v) {
    return ((unsigned)v < (unsigned)NN) ? v : 0;
}

// ---------------- tf32 helpers ----------------
__device__ __forceinline__ unsigned cvt_tf32(float f) {
    unsigned r;
    asm("cvt.rna.tf32.f32 %0, %1;" : "=r"(r) : "f"(f));
    return r;
}
__device__ __forceinline__ void mma_tf32(float* c, const unsigned* a, const unsigned* b) {
    asm volatile(
        "mma.sync.aligned.m16n8k8.row.col.f32.tf32.tf32.f32 "
        "{%0,%1,%2,%3}, {%4,%5,%6,%7}, {%8,%9}, {%0,%1,%2,%3};"
        : "+f"(c[0]), "+f"(c[1]), "+f"(c[2]), "+f"(c[3])
        : "r"(a[0]), "r"(a[1]), "r"(a[2]), "r"(a[3]), "r"(b[0]), "r"(b[1]));
}

// ---------------- degree count + inverse ----------------
__global__ void count_kernel(const int* __restrict__ ei) {
    int e = blockIdx.x * blockDim.x + threadIdx.x;
    if (e < NE) atomicAdd(&g_cnt[clampN(ei[NE + e])], 1.0f);
}
__global__ void inv_kernel() {
    int i = blockIdx.x * blockDim.x + threadIdx.x;
    if (i < NN) g_cnt[i] = 1.0f / fmaxf(g_cnt[i], 1.0f);
}

// ---------------- scatters (vector RED, proven in R7) ----------------
__global__ void scatter1_kernel(const int* __restrict__ ei,
                                const float* __restrict__ x) {
    constexpr int Q = IN_CH / 4;
    int gt = blockIdx.x * blockDim.x + threadIdx.x;
    int e = gt >> 5;
    int q = gt & 31;
    if (e >= NE) return;
    int s = clampN(ei[e]);
    int d = clampN(ei[NE + e]);
    float4 v = *((const float4*)x + (size_t)s * Q + q);
    atomicAdd((float4*)g_agg1 + (size_t)d * Q + q, v);
}
__global__ void scatter2_kernel(const int* __restrict__ ei) {
    constexpr int Q = OC / 4;
    int gt = blockIdx.x * blockDim.x + threadIdx.x;
    int e = gt >> 4;
    int q = gt & 15;
    if (e >= NE) return;
    int s = clampN(ei[e]);
    int d = clampN(ei[NE + e]);
    float4 v = *((const float4*)g_P + (size_t)s * Q + q);
    atomicAdd((float4*)g_agg2 + (size_t)d * Q + q, v);
}

// ---------------- layer-1 tf32 tensor-core GEMM ----------------
// h[n,c] = relu( mean[n,:].W1l[c,:] + x[n,:].W1r[c,:] + b1[c] )
// concat-K (K=256): kt<4 -> (agg1*inv, W1l), kt>=4 -> (x, W1r).
// BM=128, BN=128 (grid.y=2 over HID=256), BK=32. 8 warps as 4(m) x 2(n);
// warp tile 32x64 = 2 m16 x 8 n8 mma tiles.
__global__ void __launch_bounds__(256)
gemm1_tf32(const float* __restrict__ x,
           const float* __restrict__ W1l,
           const float* __restrict__ W1r,
           const float* __restrict__ b1) {
    __shared__ unsigned As[128][36];   // [row m][k], stride 36: conflict-free frags
    __shared__ unsigned Bs[128][36];   // [col n][k]

    const int tid = threadIdx.x;
    const int lane = tid & 31;
    const int warp = tid >> 5;
    const int wm = warp >> 1;          // 0..3
    const int wn = warp & 1;           // 0..1
    const int rowBase = blockIdx.x * 128;
    const int colBase = blockIdx.y * 128;

    const int lr = tid >> 1;           // load row 0..127
    const int lc = (tid & 1) * 16;     // 16 floats per thread per tile row

    float acc[2][8][4];
#pragma unroll
    for (int mi = 0; mi < 2; mi++)
#pragma unroll
        for (int ni = 0; ni < 8; ni++)
#pragma unroll
            for (int t = 0; t < 4; t++) acc[mi][ni][t] = 0.0f;

#pragma unroll 1
    for (int kt = 0; kt < 8; kt++) {
        const bool first = kt < 4;
        const int koff = first ? kt * 32 : kt * 32 - 128;
        const float* Asrc = first ? g_agg1 : x;
        const float* Bsrc = first ? W1l : W1r;

        int n = rowBase + lr; if (n >= NN) n = NN - 1;
        const float* ap = Asrc + (size_t)n * IN_CH + koff + lc;
        const float s = first ? g_cnt[n] : 1.0f;
#pragma unroll
        for (int i = 0; i < 4; i++) {
            float4 v = *(const float4*)(ap + i * 4);
            uint4 t;
            t.x = cvt_tf32(v.x * s); t.y = cvt_tf32(v.y * s);
            t.z = cvt_tf32(v.z * s); t.w = cvt_tf32(v.w * s);
            *(uint4*)&As[lr][lc + i * 4] = t;
        }
        const float* bp = Bsrc + (size_t)(colBase + lr) * IN_CH + koff + lc;
#pragma unroll
        for (int i = 0; i < 4; i++) {
            float4 v = *(const float4*)(bp + i * 4);
            uint4 t;
            t.x = cvt_tf32(v.x); t.y = cvt_tf32(v.y);
            t.z = cvt_tf32(v.z); t.w = cvt_tf32(v.w);
            *(uint4*)&Bs[lr][lc + i * 4] = t;
        }
        __syncthreads();

#pragma unroll
        for (int kk = 0; kk < 4; kk++) {
            const int k8 = kk * 8;
            const int kc = k8 + (lane & 3);
            unsigned a[2][4];
#pragma unroll
            for (int mi = 0; mi < 2; mi++) {
                int r0 = wm * 32 + mi * 16 + (lane >> 2);
                a[mi][0] = As[r0][kc];
                a[mi][1] = As[r0 + 8][kc];
                a[mi][2] = As[r0][kc + 4];
                a[mi][3] = As[r0 + 8][kc + 4];
            }
            unsigned bf[8][2];
#pragma unroll
            for (int ni = 0; ni < 8; ni++) {
                int c0 = wn * 64 + ni * 8 + (lane >> 2);
                bf[ni][0] = Bs[c0][kc];
                bf[ni][1] = Bs[c0][kc + 4];
            }
#pragma unroll
            for (int mi = 0; mi < 2; mi++)
#pragma unroll
                for (int ni = 0; ni < 8; ni++)
                    mma_tf32(acc[mi][ni], a[mi], bf[ni]);
        }
        __syncthreads();
    }

    // epilogue: + b1, ReLU, store
#pragma unroll
    for (int mi = 0; mi < 2; mi++) {
        int r0 = rowBase + wm * 32 + mi * 16 + (lane >> 2);
#pragma unroll
        for (int ni = 0; ni < 8; ni++) {
            int c = colBase + wn * 64 + ni * 8 + 2 * (lane & 3);
            float bb0 = b1[c], bb1 = b1[c + 1];
            if (r0 < NN) {
                float2 st;
                st.x = fmaxf(acc[mi][ni][0] + bb0, 0.0f);
                st.y = fmaxf(acc[mi][ni][1] + bb1, 0.0f);
                *(float2*)&g_h[(size_t)r0 * HID + c] = st;
            }
            int r1 = r0 + 8;
            if (r1 < NN) {
                float2 st;
                st.x = fmaxf(acc[mi][ni][2] + bb0, 0.0f);
                st.y = fmaxf(acc[mi][ni][3] + bb1, 0.0f);
                *(float2*)&g_h[(size_t)r1 * HID + c] = st;
            }
        }
    }
}

// ---------------- layer-2 tf32 GEMMs: C = h @ W^T (K=256, N=64) ----------------
// blockIdx.y==0: W2l -> g_P ; blockIdx.y==1: W2r -> out (raw).
// BM=128, BN=64, BK=32. 8 warps 4x2; warp tile 32x32 = 2 m16 x 4 n8.
__global__ void __launch_bounds__(256)
gemm2_tf32(const float* __restrict__ W2l,
           const float* __restrict__ W2r,
           float* __restrict__ outRaw) {
    __shared__ unsigned As[128][36];
    __shared__ unsigned Bs[64][36];

    const float* W = (blockIdx.y == 0) ? W2l : W2r;
    float* C = (blockIdx.y == 0) ? g_P : outRaw;

    const int tid = threadIdx.x;
    const int lane = tid & 31;
    const int warp = tid >> 5;
    const int wm = warp >> 1;
    const int wn = warp & 1;
    const int rowBase = blockIdx.x * 128;

    const int lr = tid >> 1;           // A: row 0..127
    const int lc = (tid & 1) * 16;
    const int br = tid >> 2;           // B: row 0..63
    const int bc = (tid & 3) * 8;      // 8 floats = 2 float4

    float acc[2][4][4];
#pragma unroll
    for (int mi = 0; mi < 2; mi++)
#pragma unroll
        for (int ni = 0; ni < 4; ni++)
#pragma unroll
            for (int t = 0; t < 4; t++) acc[mi][ni][t] = 0.0f;

#pragma unroll 1
    for (int kt = 0; kt < 8; kt++) {
        const int koff = kt * 32;
        int n = rowBase + lr; if (n >= NN) n = NN - 1;
        const float* ap = g_h + (size_t)n * HID + koff + lc;
#pragma unroll
        for (int i = 0; i < 4; i++) {
            float4 v = *(const float4*)(ap + i * 4);
            uint4 t;
            t.x = cvt_tf32(v.x); t.y = cvt_tf32(v.y);
            t.z = cvt_tf32(v.z); t.w = cvt_tf32(v.w);
            *(uint4*)&As[lr][lc + i * 4] = t;
        }
        const float* bp = W + (size_t)br * HID + koff + bc;
#pragma unroll
        for (int i = 0; i < 2; i++) {
            float4 v = *(const float4*)(bp + i * 4);
            uint4 t;
            t.x = cvt_tf32(v.x); t.y = cvt_tf32(v.y);
            t.z = cvt_tf32(v.z); t.w = cvt_tf32(v.w);
            *(uint4*)&Bs[br][bc + i * 4] = t;
        }
        __syncthreads();

#pragma unroll
        for (int kk = 0; kk < 4; kk++) {
            const int k8 = kk * 8;
            const int kc = k8 + (lane & 3);
            unsigned a[2][4];
#pragma unroll
            for (int mi = 0; mi < 2; mi++) {
                int r0 = wm * 32 + mi * 16 + (lane >> 2);
                a[mi][0] = As[r0][kc];
                a[mi][1] = As[r0 + 8][kc];
                a[mi][2] = As[r0][kc + 4];
                a[mi][3] = As[r0 + 8][kc + 4];
            }
            unsigned bf[4][2];
#pragma unroll
            for (int ni = 0; ni < 4; ni++) {
                int c0 = wn * 32 + ni * 8 + (lane >> 2);
                bf[ni][0] = Bs[c0][kc];
                bf[ni][1] = Bs[c0][kc + 4];
            }
#pragma unroll
            for (int mi = 0; mi < 2; mi++)
#pragma unroll
                for (int ni = 0; ni < 4; ni++)
                    mma_tf32(acc[mi][ni], a[mi], bf[ni]);
        }
        __syncthreads();
    }

#pragma unroll
    for (int mi = 0; mi < 2; mi++) {
        int r0 = rowBase + wm * 32 + mi * 16 + (lane >> 2);
#pragma unroll
        for (int ni = 0; ni < 4; ni++) {
            int c = wn * 32 + ni * 8 + 2 * (lane & 3);
            if (r0 < NN) {
                float2 st; st.x = acc[mi][ni][0]; st.y = acc[mi][ni][1];
                *(float2*)&C[(size_t)r0 * OC + c] = st;
            }
            int r1 = r0 + 8;
            if (r1 < NN) {
                float2 st; st.x = acc[mi][ni][2]; st.y = acc[mi][ni][3];
                *(float2*)&C[(size_t)r1 * OC + c] = st;
            }
        }
    }
}

// ---------------- finalize: out += inv * agg2 + b2 ----------------
__global__ void finalize_kernel(const float* __restrict__ b2,
                                float* __restrict__ out) {
    int i = blockIdx.x * blockDim.x + threadIdx.x;
    if (i >= NN * (OC / 4)) return;
    int n = i / (OC / 4);
    int c4 = i % (OC / 4);
    float inv = g_cnt[n];
    float4 o = ((float4*)out)[i];
    float4 a = ((const float4*)g_agg2)[i];
    float4 b = ((const float4*)b2)[c4];
    o.x += inv * a.x + b.x;
    o.y += inv * a.y + b.y;
    o.z += inv * a.z + b.z;
    o.w += inv * a.w + b.w;
    ((float4*)out)[i] = o;
}

// ---------------- launch ----------------
extern "C" void kernel_launch(void* const* d_in, const int* in_sizes, int n_in,
                              void* d_out, int out_size) {
    const float* x   = (const float*)d_in[0];
    const int*   ei  = (const int*)d_in[1];      // int32
    const float* W1l = (const float*)d_in[2];
    const float* b1  = (const float*)d_in[3];
    const float* W1r = (const float*)d_in[4];
    const float* W2l = (const float*)d_in[5];
    const float* b2  = (const float*)d_in[6];
    const float* W2r = (const float*)d_in[7];
    float* out = (float*)d_out;

    zero_kernel<<<(unsigned)((ZERO_F4 + 255) / 256), 256>>>();

    count_kernel<<<(NE + 255) / 256, 256>>>(ei);
    inv_kernel<<<(NN + 255) / 256, 256>>>();

    scatter1_kernel<<<(NE * 32 + 255) / 256, 256>>>(ei, x);

    gemm1_tf32<<<dim3((NN + 127) / 128, 2), 256>>>(x, W1l, W1r, b1);

    gemm2_tf32<<<dim3((NN + 127) / 128, 2), 256>>>(W2l, W2r, out);

    scatter2_kernel<<<(NE * 16 + 255) / 256, 256>>>(ei);

    finalize_kernel<<<(NN * (OC / 4) + 255) / 256, 256>>>(b2, out);
}